// round 1
// baseline (speedup 1.0000x reference)
#include <cuda_runtime.h>
#include <math.h>

// Problem constants
#define BMAX 2048
#define SS   8
#define NN   32
#define DD   64
#define NP   496          // 32*31/2

typedef unsigned long long ull;

// Scratch: pre[b][k][n], k in 0..127 (0-63: fi@W1a col k, 64-127: fj@W1b col k-64)
__device__ float g_pre[(size_t)BMAX * 128 * NN];

// ---------------- packed f32x2 helpers (sm_100+/sm_103a) ----------------
__device__ __forceinline__ ull pk2(float a, float b) {
    ull r; asm("mov.b64 %0, {%1,%2};" : "=l"(r) : "f"(a), "f"(b)); return r;
}
__device__ __forceinline__ void fma2(ull &d, ull a, ull b) {
    asm("fma.rn.f32x2 %0, %1, %2, %0;" : "+l"(d) : "l"(a), "l"(b));
}
__device__ __forceinline__ float2 upk(ull a) {
    float2 f; asm("mov.b64 {%0,%1}, %2;" : "=f"(f.x), "=f"(f.y) : "l"(a)); return f;
}

__device__ __forceinline__ float wrapang(float d) {
    // == atan2f(sinf(d), cosf(d)) up to rounding: wrap to [-pi, pi]
    return fmaf(-6.283185307179586f, rintf(d * 0.15915494309189535f), d);
}
__device__ __forceinline__ float gelu_exact(float x) {
    return 0.5f * x * (1.0f + erff(x * 0.7071067811865476f));
}
__device__ __forceinline__ float sigm(float x) {
    return 1.0f / (1.0f + expf(-x));
}

// ---------------- Kernel 1: pre[b][k][n] = feats[b][n] . Wcat[:,k] ----------------
// Wcat[d][k] = W1[d][k] for k<64, W1[64+d][k-64] for k>=64
__global__ __launch_bounds__(128, 8)
void pre_kernel(const float* __restrict__ cel, const float* __restrict__ W1,
                float* __restrict__ pre) {
    const int b = blockIdx.x;
    const int t = threadIdx.x;   // t = output column k, 0..127

    __shared__ float fS[NN * DD];        // 8 KB  feats for this batch
    __shared__ float oS[128 * 33];       // ~16.9 KB padded staging

    const float* feats = cel + (((size_t)b * SS + (SS - 1)) * NN) * DD;
    // cooperative load of feats (2048 floats, 128 threads x 4 float4)
#pragma unroll
    for (int u = 0; u < 4; u++)
        ((float4*)fS)[t + u * 128] = ((const float4*)feats)[t + u * 128];

    // weight column into registers (coalesced: consecutive t -> consecutive addr)
    float wk[DD];
    const float* wcol = (t < 64) ? (W1 + t) : (W1 + 64 * 64 + (t - 64));
#pragma unroll
    for (int d = 0; d < DD; d++) wk[d] = wcol[(size_t)d * 64];

    __syncthreads();

#pragma unroll 2
    for (int n = 0; n < NN; n++) {
        const float4* fr = (const float4*)(fS + n * DD);
        float a = 0.0f;
#pragma unroll
        for (int d4 = 0; d4 < 16; d4++) {
            float4 f = fr[d4];
            a = fmaf(f.x, wk[4 * d4 + 0], a);
            a = fmaf(f.y, wk[4 * d4 + 1], a);
            a = fmaf(f.z, wk[4 * d4 + 2], a);
            a = fmaf(f.w, wk[4 * d4 + 3], a);
        }
        oS[t * 33 + n] = a;   // stride 33: conflict-free
    }
    __syncthreads();

    float* ob = pre + (size_t)b * (128 * NN);
#pragma unroll
    for (int u = 0; u < 32; u++) {
        int idx = t + u * 128;
        ob[idx] = oS[(idx >> 5) * 33 + (idx & 31)];
    }
}

// ---------------- Kernel 2: per-pair MLP + gate + symmetric scatter ----------------
__global__ __launch_bounds__(512, 1)
void pair_kernel(const float* __restrict__ pre,
                 const float* __restrict__ theta, const float* __restrict__ phi,
                 const float* __restrict__ vel,   const float* __restrict__ rad,
                 const float* __restrict__ lon,
                 const float* __restrict__ W1, const float* __restrict__ b1,
                 const float* __restrict__ W2, const float* __restrict__ b2,
                 const float* __restrict__ W3, const float* __restrict__ b3,
                 const float* __restrict__ pw,
                 float* __restrict__ out) {
    const int b = blockIdx.x;
    const int t = threadIdx.x;

    __shared__ float preS[128 * NN];     // 16 KB   preS[k*32 + n]
    __shared__ float W2S[64 * NN];       // 8 KB    W2S[k*32 + n]
    __shared__ float W1cS[64 * 8];       // 2 KB    [k][0..5]=W1 tail rows, [k][6]=b1[k], [k][7]=0
    __shared__ float b2S[32], W3S[32], pwS[8];
    __shared__ float thS[32], phS[32], veS[32], raS[32], loS[32];
    __shared__ float cthS[32], sthS[32], cphS[32], sphS[32];
    __shared__ float adjS[32 * 33];
    __shared__ float b3S;

    // ---- stage shared ----
    const float* preB = pre + (size_t)b * (128 * NN);
    ((float4*)preS)[t]       = ((const float4*)preB)[t];
    ((float4*)preS)[t + 512] = ((const float4*)preB)[t + 512];
    ((float4*)W2S)[t] = ((const float4*)W2)[t];          // 2048 floats = 512 float4
    {
        int k = t >> 3, s = t & 7;
        float v = 0.0f;
        if (s < 6)       v = W1[(size_t)(128 + s) * 64 + k];
        else if (s == 6) v = b1[k];
        W1cS[t] = v;
    }
    if (t < 32) {
        b2S[t] = b2[t];
        W3S[t] = W3[t];
        float tht = theta[b * NN + t], pht = phi[b * NN + t];
        thS[t] = tht; phS[t] = pht;
        veS[t] = vel[b * NN + t];
        raS[t] = rad[b * NN + t];
        loS[t] = lon[b * NN + t];
        float s_, c_;
        sincosf(tht, &s_, &c_); sthS[t] = s_; cthS[t] = c_;
        sincosf(pht, &s_, &c_); sphS[t] = s_; cphS[t] = c_;
    }
    if (t < 6)  pwS[t] = pw[t];
    if (t == 0) b3S = b3[0];
    __syncthreads();

    if (t < NP) {
        // pair index -> (i, j), i<j. f(i) = i*(63-i)/2; boundary sqrt args are
        // exact squares (63-2i)^2 so sqrtf is exact there.
        float pf = (float)t;
        int i = (int)((63.0f - sqrtf(3969.0f - 8.0f * pf)) * 0.5f);
        int base = (i * (63 - i)) >> 1;
        int j = i + 1 + (t - base);

        float td  = wrapang(thS[i] - thS[j]);
        float pd  = wrapang(phS[i] - phS[j]);
        float vd  = veS[i] - veS[j];
        float rr  = raS[i] / (raS[j] + 1e-8f);
        float ldv = wrapang(loS[i] - loS[j]);
        // cos(td)*cos(pd) via product identities (cos of wrapped == cos of raw diff)
        float pr  = (cthS[i] * cthS[j] + sthS[i] * sthS[j]) *
                    (cphS[i] * cphS[j] + sphS[i] * sphS[j]);

        float gs = pwS[0] * fabsf(td) + pwS[1] * fabsf(pd) + pwS[2] * fabsf(vd)
                 + pwS[3] * fabsf(rr - 1.0f) + pwS[4] * fabsf(ldv) + pwS[5] * fabsf(pr);
        float gate = sigm(gs);

        ull acc[16];
#pragma unroll
        for (int m = 0; m < 16; m++) acc[m] = pk2(b2S[2 * m], b2S[2 * m + 1]);

#pragma unroll 4
        for (int k = 0; k < 64; k++) {
            float h = preS[k * NN + i] + preS[(64 + k) * NN + j];
            float4 wA = ((const float4*)W1cS)[k * 2];
            float4 wB = ((const float4*)W1cS)[k * 2 + 1];
            h = h + wB.z;                       // + b1[k]
            h = fmaf(td,  wA.x, h);
            h = fmaf(pd,  wA.y, h);
            h = fmaf(vd,  wA.z, h);
            h = fmaf(rr,  wA.w, h);
            h = fmaf(ldv, wB.x, h);
            h = fmaf(pr,  wB.y, h);
            float g = gelu_exact(h);
            ull g2 = pk2(g, g);
            const ulonglong2* w2r = (const ulonglong2*)(W2S + k * NN);
#pragma unroll
            for (int m = 0; m < 8; m++) {
                ulonglong2 w = w2r[m];          // 4 W2 values, two packed f32x2
                fma2(acc[2 * m],     g2, w.x);
                fma2(acc[2 * m + 1], g2, w.y);
            }
        }

        float e = b3S;
#pragma unroll
        for (int m = 0; m < 16; m++) {
            float2 v = upk(acc[m]);
            float g0 = gelu_exact(v.x);
            float g1 = gelu_exact(v.y);
            e = fmaf(g0, W3S[2 * m], e);
            e = fmaf(g1, W3S[2 * m + 1], e);
        }
        float fe = sigm(e) * gate;

        adjS[i * 33 + j] = fe;
        adjS[j * 33 + i] = fe;
    }
    if (t < 32) adjS[t * 33 + t] = 0.0f;
    __syncthreads();

    float* outB = out + (size_t)b * (NN * NN);
    {
        int idx = t;
        outB[idx] = adjS[(idx >> 5) * 33 + (idx & 31)];
        idx = t + 512;
        outB[idx] = adjS[(idx >> 5) * 33 + (idx & 31)];
    }
}

// ---------------- launch ----------------
extern "C" void kernel_launch(void* const* d_in, const int* in_sizes, int n_in,
                              void* d_out, int out_size) {
    const float* cel   = (const float*)d_in[0];
    const float* theta = (const float*)d_in[1];
    const float* phi   = (const float*)d_in[2];
    const float* vel   = (const float*)d_in[3];
    const float* rad   = (const float*)d_in[4];
    const float* lon   = (const float*)d_in[5];
    const float* W1    = (const float*)d_in[6];
    const float* b1    = (const float*)d_in[7];
    const float* W2    = (const float*)d_in[8];
    const float* b2    = (const float*)d_in[9];
    const float* W3    = (const float*)d_in[10];
    const float* b3    = (const float*)d_in[11];
    const float* pw    = (const float*)d_in[12];
    float* out = (float*)d_out;

    int B = in_sizes[0] / (SS * NN * DD);
    if (B > BMAX) B = BMAX;

    float* pre;
    cudaGetSymbolAddress((void**)&pre, g_pre);

    pre_kernel<<<B, 128>>>(cel, W1, pre);
    pair_kernel<<<B, 512>>>(pre, theta, phi, vel, rad, lon,
                            W1, b1, W2, b2, W3, b3, pw, out);
}

// round 2
// speedup vs baseline: 2.0759x; 2.0759x over previous
#include <cuda_runtime.h>
#include <math.h>

// Problem constants
#define BMAX 2048
#define SS   8
#define NN   32
#define DD   64
#define NP   496          // 32*31/2

typedef unsigned long long ull;

// Scratch: interleaved layout. float index = part*2048 + (kk>>1)*64 + 2*n + (kk&1),
// where part = k>=64 (fj half), kk = k & 63.  As ull (f32 pairs over k,k+1):
// ull index = part*1024 + k2*32 + n.
__device__ float g_pre[(size_t)BMAX * 128 * NN];

// ---------------- packed f32x2 helpers (sm_103a) ----------------
__device__ __forceinline__ ull pk2(float a, float b) {
    ull r; asm("mov.b64 %0, {%1,%2};" : "=l"(r) : "f"(a), "f"(b)); return r;
}
__device__ __forceinline__ void fma2(ull &d, ull a, ull b) {
    asm("fma.rn.f32x2 %0, %1, %2, %0;" : "+l"(d) : "l"(a), "l"(b));
}
__device__ __forceinline__ ull add2(ull a, ull b) {
    ull r; asm("add.rn.f32x2 %0, %1, %2;" : "=l"(r) : "l"(a), "l"(b)); return r;
}
__device__ __forceinline__ float2 upk(ull a) {
    float2 f; asm("mov.b64 {%0,%1}, %2;" : "=f"(f.x), "=f"(f.y) : "l"(a)); return f;
}

__device__ __forceinline__ float wrapang(float d) {
    // == atan2f(sinf(d), cosf(d)) up to rounding: wrap to [-pi, pi]
    return fmaf(-6.283185307179586f, rintf(d * 0.15915494309189535f), d);
}

// Branch-free gelu (exact erf via Abramowitz-Stegun 7.1.26, |err| <= 1.5e-7)
__device__ __forceinline__ float gelu_f(float x) {
    float z  = 0.7071067811865476f * x;
    float az = fabsf(z);
    float w  = fmaf(0.3275911f, az, 1.0f);
    float t;  asm("rcp.approx.f32 %0, %1;" : "=f"(t) : "f"(w));
    float y  = fmaf(1.061405429f, t, -1.453152027f);
    y = fmaf(y, t, 1.421413741f);
    y = fmaf(y, t, -0.284496736f);
    y = fmaf(y, t, 0.254829592f);
    y = y * t;
    float e  = __expf(-z * z);
    float er = fmaf(-y, e, 1.0f);          // erf(|z|)
    er = copysignf(er, z);
    float hx = 0.5f * x;
    return fmaf(hx, er, hx);               // 0.5*x*(1+erf(z))
}
__device__ __forceinline__ float sigm(float x) {
    return 1.0f / (1.0f + __expf(-x));
}

// ---------------- Kernel 1: pre (interleaved layout), f32x2, 4 acc chains ----------------
__global__ __launch_bounds__(256)
void pre_kernel(const float* __restrict__ cel, const float* __restrict__ W1,
                float* __restrict__ pre) {
    const int b = blockIdx.x;
    const int t = threadIdx.x;
    const int k = t & 127;       // output column 0..127
    const int half = t >> 7;     // n-range selector

    __shared__ __align__(16) float fS[NN * DD];      // 8 KB
    __shared__ float oS[4096 + 64];                  // padded staging

    const float* feats = cel + (((size_t)b * SS + (SS - 1)) * NN) * DD;
    ((float4*)fS)[t]       = ((const float4*)feats)[t];
    ((float4*)fS)[t + 256] = ((const float4*)feats)[t + 256];

    // packed weight column {W[2d][k], W[2d+1][k]}
    const float* wcol = (k < 64) ? (W1 + k) : (W1 + 64 * 64 + (k - 64));
    ull wk2[32];
#pragma unroll
    for (int d2 = 0; d2 < 32; d2++)
        wk2[d2] = pk2(wcol[(size_t)(2 * d2) * 64], wcol[(size_t)(2 * d2 + 1) * 64]);

    __syncthreads();

    const int kk = k & 63, part = k >> 6, kb = k & 1;
    const int obase = part * 2048 + (kk >> 1) * 64 + kb;

    for (int n = half * 16; n < half * 16 + 16; n++) {
        const ull* fr = (const ull*)(fS + n * DD);
        ull a0 = 0ull, a1 = 0ull, a2 = 0ull, a3 = 0ull;
#pragma unroll
        for (int d2 = 0; d2 < 32; d2 += 4) {
            fma2(a0, fr[d2],     wk2[d2]);
            fma2(a1, fr[d2 + 1], wk2[d2 + 1]);
            fma2(a2, fr[d2 + 2], wk2[d2 + 2]);
            fma2(a3, fr[d2 + 3], wk2[d2 + 3]);
        }
        a0 = add2(a0, a1); a2 = add2(a2, a3); a0 = add2(a0, a2);
        float2 v = upk(a0);
        float a = v.x + v.y;
        int idx = obase + 2 * n;
        oS[idx + (idx >> 6)] = a;    // pad every 64 to break bank conflicts
    }
    __syncthreads();

    float* ob = pre + (size_t)b * 4096;
#pragma unroll
    for (int u = 0; u < 16; u++) {
        int i2 = t + u * 256;
        ob[i2] = oS[i2 + (i2 >> 6)];
    }
}

// ---------------- Kernel 2: per-pair MLP + gate + symmetric scatter ----------------
__global__ __launch_bounds__(512, 1)
void pair_kernel(const float* __restrict__ pre,
                 const float* __restrict__ theta, const float* __restrict__ phi,
                 const float* __restrict__ vel,   const float* __restrict__ rad,
                 const float* __restrict__ lon,
                 const float* __restrict__ W1, const float* __restrict__ b1,
                 const float* __restrict__ W2, const float* __restrict__ b2,
                 const float* __restrict__ W3, const float* __restrict__ b3,
                 const float* __restrict__ pw,
                 float* __restrict__ out) {
    const int b = blockIdx.x;
    const int t = threadIdx.x;

    __shared__ __align__(16) ull  preS2[2048];       // 16 KB interleaved pre
    __shared__ __align__(16) float W2S[64 * NN];     // 8 KB   W2S[k*32 + m]
    __shared__ __align__(16) ull  W1cS[32 * 8];      // 2 KB   per k2: 6 coeff pairs, b1 pair, pad
    __shared__ float b2S[32], W3S[32], pwS[8];
    __shared__ float thS[32], phS[32], veS[32], raS[32], loS[32];
    __shared__ float cthS[32], sthS[32], cphS[32], sphS[32];
    __shared__ float adjS[32 * 33];
    __shared__ float b3S;

    // ---- stage shared ----
    const float* preB = pre + (size_t)b * 4096;
    ((float4*)preS2)[t]       = ((const float4*)preB)[t];
    ((float4*)preS2)[t + 512] = ((const float4*)preB)[t + 512];
    ((float4*)W2S)[t] = ((const float4*)W2)[t];          // 2048 floats
    if (t < 256) {
        int k2 = t >> 3, s = t & 7, k = 2 * k2;
        float lo = 0.0f, hi = 0.0f;
        if (s < 6)       { lo = W1[(size_t)(128 + s) * 64 + k]; hi = W1[(size_t)(128 + s) * 64 + k + 1]; }
        else if (s == 6) { lo = b1[k]; hi = b1[k + 1]; }
        W1cS[t] = pk2(lo, hi);
    }
    if (t < 32) {
        b2S[t] = b2[t];
        W3S[t] = W3[t];
        float tht = theta[b * NN + t], pht = phi[b * NN + t];
        thS[t] = tht; phS[t] = pht;
        veS[t] = vel[b * NN + t];
        raS[t] = rad[b * NN + t];
        loS[t] = lon[b * NN + t];
        float s_, c_;
        sincosf(tht, &s_, &c_); sthS[t] = s_; cthS[t] = c_;
        sincosf(pht, &s_, &c_); sphS[t] = s_; cphS[t] = c_;
    }
    if (t < 6)  pwS[t] = pw[t];
    if (t == 0) b3S = b3[0];
    __syncthreads();

    if (t < NP) {
        // pair index -> (i, j), i<j
        float pf = (float)t;
        int i = (int)((63.0f - sqrtf(3969.0f - 8.0f * pf)) * 0.5f);
        int base = (i * (63 - i)) >> 1;
        int j = i + 1 + (t - base);

        float td  = wrapang(thS[i] - thS[j]);
        float pd  = wrapang(phS[i] - phS[j]);
        float vd  = veS[i] - veS[j];
        float rr  = __fdividef(raS[i], raS[j] + 1e-8f);
        float ldv = wrapang(loS[i] - loS[j]);
        float pr  = (cthS[i] * cthS[j] + sthS[i] * sthS[j]) *
                    (cphS[i] * cphS[j] + sphS[i] * sphS[j]);

        float gs = pwS[0] * fabsf(td) + pwS[1] * fabsf(pd) + pwS[2] * fabsf(vd)
                 + pwS[3] * fabsf(rr - 1.0f) + pwS[4] * fabsf(ldv) + pwS[5] * fabsf(pr);
        float gate = sigm(gs);

        ull td2 = pk2(td, td), pd2 = pk2(pd, pd), vd2 = pk2(vd, vd);
        ull rr2 = pk2(rr, rr), ld2 = pk2(ldv, ldv), pr2 = pk2(pr, pr);

        ull acc[16];
#pragma unroll
        for (int m = 0; m < 16; m++) acc[m] = pk2(b2S[2 * m], b2S[2 * m + 1]);

        const ull* pFi = preS2 + i;            // + k2*32
        const ull* pFj = preS2 + 1024 + j;     // + k2*32

#pragma unroll 4
        for (int k2 = 0; k2 < 32; k2++) {
            ull h2 = add2(pFi[k2 * 32], pFj[k2 * 32]);   // {h_k, h_k+1} node parts
            const ull* w = W1cS + k2 * 8;
            h2 = add2(h2, w[6]);                         // + b1 pair
            fma2(h2, td2, w[0]);
            fma2(h2, pd2, w[1]);
            fma2(h2, vd2, w[2]);
            fma2(h2, rr2, w[3]);
            fma2(h2, ld2, w[4]);
            fma2(h2, pr2, w[5]);
            float2 hv = upk(h2);
            float g0 = gelu_f(hv.x);
            float g1 = gelu_f(hv.y);
            ull g20 = pk2(g0, g0);
            ull g21 = pk2(g1, g1);
            const ull* w2a = (const ull*)(W2S + (2 * k2) * NN);
            const ull* w2b = (const ull*)(W2S + (2 * k2 + 1) * NN);
#pragma unroll
            for (int m = 0; m < 16; m++) fma2(acc[m], g20, w2a[m]);
#pragma unroll
            for (int m = 0; m < 16; m++) fma2(acc[m], g21, w2b[m]);
        }

        float e = b3S;
#pragma unroll
        for (int m = 0; m < 16; m++) {
            float2 v = upk(acc[m]);
            e = fmaf(gelu_f(v.x), W3S[2 * m], e);
            e = fmaf(gelu_f(v.y), W3S[2 * m + 1], e);
        }
        float fe = sigm(e) * gate;

        adjS[i * 33 + j] = fe;
        adjS[j * 33 + i] = fe;
    }
    if (t < 32) adjS[t * 33 + t] = 0.0f;
    __syncthreads();

    float* outB = out + (size_t)b * (NN * NN);
    {
        int idx = t;
        outB[idx] = adjS[(idx >> 5) * 33 + (idx & 31)];
        idx = t + 512;
        outB[idx] = adjS[(idx >> 5) * 33 + (idx & 31)];
    }
}

// ---------------- launch ----------------
extern "C" void kernel_launch(void* const* d_in, const int* in_sizes, int n_in,
                              void* d_out, int out_size) {
    const float* cel   = (const float*)d_in[0];
    const float* theta = (const float*)d_in[1];
    const float* phi   = (const float*)d_in[2];
    const float* vel   = (const float*)d_in[3];
    const float* rad   = (const float*)d_in[4];
    const float* lon   = (const float*)d_in[5];
    const float* W1    = (const float*)d_in[6];
    const float* b1    = (const float*)d_in[7];
    const float* W2    = (const float*)d_in[8];
    const float* b2    = (const float*)d_in[9];
    const float* W3    = (const float*)d_in[10];
    const float* b3    = (const float*)d_in[11];
    const float* pw    = (const float*)d_in[12];
    float* out = (float*)d_out;

    int B = in_sizes[0] / (SS * NN * DD);
    if (B > BMAX) B = BMAX;

    float* pre;
    cudaGetSymbolAddress((void**)&pre, g_pre);

    pre_kernel<<<B, 256>>>(cel, W1, pre);
    pair_kernel<<<B, 512>>>(pre, theta, phi, vel, rad, lon,
                            W1, b1, W2, b2, W3, b3, pw, out);
}

// round 3
// speedup vs baseline: 2.1129x; 1.0178x over previous
#include <cuda_runtime.h>
#include <math.h>

// Problem constants
#define BMAX 2048
#define SS   8
#define NN   32
#define DD   64
#define NP   496          // 32*31/2

typedef unsigned long long ull;

// Scratch: interleaved layout. As ull (f32 pairs over k,k+1):
// ull index = part*1024 + k2*32 + n   (part: 0 = fi-half, 1 = fj-half)
__device__ float g_pre[(size_t)BMAX * 128 * NN];

// ---------------- packed f32x2 helpers (sm_103a) ----------------
__device__ __forceinline__ ull pk2(float a, float b) {
    ull r; asm("mov.b64 %0, {%1,%2};" : "=l"(r) : "f"(a), "f"(b)); return r;
}
__device__ __forceinline__ void fma2(ull &d, ull a, ull b) {
    asm("fma.rn.f32x2 %0, %1, %2, %0;" : "+l"(d) : "l"(a), "l"(b));
}
__device__ __forceinline__ ull add2(ull a, ull b) {
    ull r; asm("add.rn.f32x2 %0, %1, %2;" : "=l"(r) : "l"(a), "l"(b)); return r;
}
__device__ __forceinline__ float2 upk(ull a) {
    float2 f; asm("mov.b64 {%0,%1}, %2;" : "=f"(f.x), "=f"(f.y) : "l"(a)); return f;
}

__device__ __forceinline__ float wrapang(float d) {
    return fmaf(-6.283185307179586f, rintf(d * 0.15915494309189535f), d);
}

// Branch-free gelu (erf via Abramowitz-Stegun 7.1.26, |err| <= 1.5e-7)
__device__ __forceinline__ float gelu_f(float x) {
    float z  = 0.7071067811865476f * x;
    float az = fabsf(z);
    float w  = fmaf(0.3275911f, az, 1.0f);
    float t;  asm("rcp.approx.f32 %0, %1;" : "=f"(t) : "f"(w));
    float y  = fmaf(1.061405429f, t, -1.453152027f);
    y = fmaf(y, t, 1.421413741f);
    y = fmaf(y, t, -0.284496736f);
    y = fmaf(y, t, 0.254829592f);
    y = y * t;
    float e  = __expf(-z * z);
    float er = fmaf(-y, e, 1.0f);          // erf(|z|)
    er = copysignf(er, z);
    float hx = 0.5f * x;
    return fmaf(hx, er, hx);               // 0.5*x*(1+erf(z))
}
__device__ __forceinline__ float sigm(float x) {
    return 1.0f / (1.0f + __expf(-x));
}

// ---------------- Kernel 1: pre (interleaved layout), f32x2, 4 acc chains ----------------
__global__ __launch_bounds__(256)
void pre_kernel(const float* __restrict__ cel, const float* __restrict__ W1,
                float* __restrict__ pre) {
    const int b = blockIdx.x;
    const int t = threadIdx.x;
    const int k = t & 127;       // output column 0..127
    const int half = t >> 7;     // n-range selector

    __shared__ __align__(16) float fS[NN * DD];      // 8 KB
    __shared__ float oS[4096 + 64];                  // padded staging

    const float* feats = cel + (((size_t)b * SS + (SS - 1)) * NN) * DD;
    ((float4*)fS)[t]       = ((const float4*)feats)[t];
    ((float4*)fS)[t + 256] = ((const float4*)feats)[t + 256];

    // packed weight column {W[2d][k], W[2d+1][k]}
    const float* wcol = (k < 64) ? (W1 + k) : (W1 + 64 * 64 + (k - 64));
    ull wk2[32];
#pragma unroll
    for (int d2 = 0; d2 < 32; d2++)
        wk2[d2] = pk2(wcol[(size_t)(2 * d2) * 64], wcol[(size_t)(2 * d2 + 1) * 64]);

    __syncthreads();

    const int kk = k & 63, part = k >> 6, kb = k & 1;
    const int obase = part * 2048 + (kk >> 1) * 64 + kb;

    for (int n = half * 16; n < half * 16 + 16; n++) {
        const ull* fr = (const ull*)(fS + n * DD);
        ull a0 = 0ull, a1 = 0ull, a2 = 0ull, a3 = 0ull;
#pragma unroll
        for (int d2 = 0; d2 < 32; d2 += 4) {
            fma2(a0, fr[d2],     wk2[d2]);
            fma2(a1, fr[d2 + 1], wk2[d2 + 1]);
            fma2(a2, fr[d2 + 2], wk2[d2 + 2]);
            fma2(a3, fr[d2 + 3], wk2[d2 + 3]);
        }
        a0 = add2(a0, a1); a2 = add2(a2, a3); a0 = add2(a0, a2);
        float2 v = upk(a0);
        float a = v.x + v.y;
        int idx = obase + 2 * n;
        oS[idx + (idx >> 6)] = a;    // pad every 64 to break bank conflicts
    }
    __syncthreads();

    float* ob = pre + (size_t)b * 4096;
#pragma unroll
    for (int u = 0; u < 16; u++) {
        int i2 = t + u * 256;
        ob[i2] = oS[i2 + (i2 >> 6)];
    }
}

// ---------------- Kernel 2: 2 pairs per thread, 256 threads ----------------
__global__ __launch_bounds__(256, 1)
void pair_kernel(const float* __restrict__ pre,
                 const float* __restrict__ theta, const float* __restrict__ phi,
                 const float* __restrict__ vel,   const float* __restrict__ rad,
                 const float* __restrict__ lon,
                 const float* __restrict__ W1, const float* __restrict__ b1,
                 const float* __restrict__ W2, const float* __restrict__ b2,
                 const float* __restrict__ W3, const float* __restrict__ b3,
                 const float* __restrict__ pw,
                 float* __restrict__ out) {
    const int b = blockIdx.x;
    const int t = threadIdx.x;

    __shared__ __align__(16) ull  preS2[2048];       // 16 KB interleaved pre
    __shared__ __align__(16) float W2S[64 * NN];     // 8 KB
    __shared__ __align__(16) ull  W1cS[32 * 8];      // 2 KB: per k2: 6 coeff pairs, b1 pair, pad
    __shared__ float b2S[32], W3S[32], pwS[8];
    __shared__ float thS[32], phS[32], veS[32], raS[32], loS[32];
    __shared__ float cthS[32], sthS[32], cphS[32], sphS[32];
    __shared__ float adjS[32 * 33];
    __shared__ float b3S;

    // ---- stage shared ----
    const float* preB = pre + (size_t)b * 4096;
#pragma unroll
    for (int u = 0; u < 4; u++)
        ((float4*)preS2)[t + u * 256] = ((const float4*)preB)[t + u * 256];
    ((float4*)W2S)[t]       = ((const float4*)W2)[t];
    ((float4*)W2S)[t + 256] = ((const float4*)W2)[t + 256];
    {
        int k2 = t >> 3, s = t & 7, k = 2 * k2;
        float lo = 0.0f, hi = 0.0f;
        if (s < 6)       { lo = W1[(size_t)(128 + s) * 64 + k]; hi = W1[(size_t)(128 + s) * 64 + k + 1]; }
        else if (s == 6) { lo = b1[k]; hi = b1[k + 1]; }
        W1cS[t] = pk2(lo, hi);
    }
    if (t < 32) {
        b2S[t] = b2[t];
        W3S[t] = W3[t];
        float tht = theta[b * NN + t], pht = phi[b * NN + t];
        thS[t] = tht; phS[t] = pht;
        veS[t] = vel[b * NN + t];
        raS[t] = rad[b * NN + t];
        loS[t] = lon[b * NN + t];
        float s_, c_;
        sincosf(tht, &s_, &c_); sthS[t] = s_; cthS[t] = c_;
        sincosf(pht, &s_, &c_); sphS[t] = s_; cphS[t] = c_;
    }
    if (t < 6)  pwS[t] = pw[t];
    if (t == 0) b3S = b3[0];
    __syncthreads();

    if (t < 248) {
        // two pairs: pA = t, pB = t + 248
        int iA, jA, iB, jB;
        {
            float pf = (float)t;
            iA = (int)((63.0f - sqrtf(3969.0f - 8.0f * pf)) * 0.5f);
            jA = iA + 1 + (t - ((iA * (63 - iA)) >> 1));
            int tb = t + 248;
            pf = (float)tb;
            iB = (int)((63.0f - sqrtf(3969.0f - 8.0f * pf)) * 0.5f);
            jB = iB + 1 + (tb - ((iB * (63 - iB)) >> 1));
        }

        // scalar features per pair
        float tdA = wrapang(thS[iA] - thS[jA]);
        float pdA = wrapang(phS[iA] - phS[jA]);
        float vdA = veS[iA] - veS[jA];
        float rrA = __fdividef(raS[iA], raS[jA] + 1e-8f);
        float ldA = wrapang(loS[iA] - loS[jA]);
        float prA = (cthS[iA] * cthS[jA] + sthS[iA] * sthS[jA]) *
                    (cphS[iA] * cphS[jA] + sphS[iA] * sphS[jA]);
        float tdB = wrapang(thS[iB] - thS[jB]);
        float pdB = wrapang(phS[iB] - phS[jB]);
        float vdB = veS[iB] - veS[jB];
        float rrB = __fdividef(raS[iB], raS[jB] + 1e-8f);
        float ldB = wrapang(loS[iB] - loS[jB]);
        float prB = (cthS[iB] * cthS[jB] + sthS[iB] * sthS[jB]) *
                    (cphS[iB] * cphS[jB] + sphS[iB] * sphS[jB]);

        float gateA = sigm(pwS[0] * fabsf(tdA) + pwS[1] * fabsf(pdA) + pwS[2] * fabsf(vdA)
                         + pwS[3] * fabsf(rrA - 1.0f) + pwS[4] * fabsf(ldA) + pwS[5] * fabsf(prA));
        float gateB = sigm(pwS[0] * fabsf(tdB) + pwS[1] * fabsf(pdB) + pwS[2] * fabsf(vdB)
                         + pwS[3] * fabsf(rrB - 1.0f) + pwS[4] * fabsf(ldB) + pwS[5] * fabsf(prB));

        ull tdA2 = pk2(tdA, tdA), pdA2 = pk2(pdA, pdA), vdA2 = pk2(vdA, vdA);
        ull rrA2 = pk2(rrA, rrA), ldA2 = pk2(ldA, ldA), prA2 = pk2(prA, prA);
        ull tdB2 = pk2(tdB, tdB), pdB2 = pk2(pdB, pdB), vdB2 = pk2(vdB, vdB);
        ull rrB2 = pk2(rrB, rrB), ldB2 = pk2(ldB, ldB), prB2 = pk2(prB, prB);

        ull accA[16], accB[16];
#pragma unroll
        for (int m = 0; m < 16; m++) {
            ull b0 = pk2(b2S[2 * m], b2S[2 * m + 1]);
            accA[m] = b0; accB[m] = b0;
        }

        const ull* pFiA = preS2 + iA;
        const ull* pFjA = preS2 + 1024 + jA;
        const ull* pFiB = preS2 + iB;
        const ull* pFjB = preS2 + 1024 + jB;

#pragma unroll 1
        for (int k2 = 0; k2 < 32; k2++) {
            ull hA = add2(pFiA[k2 * 32], pFjA[k2 * 32]);
            ull hB = add2(pFiB[k2 * 32], pFjB[k2 * 32]);
            const ulonglong2* w = (const ulonglong2*)(W1cS + k2 * 8);
            ulonglong2 w01 = w[0], w23 = w[1], w45 = w[2], w6x = w[3];
            hA = add2(hA, w6x.x);
            fma2(hA, tdA2, w01.x); fma2(hA, pdA2, w01.y);
            fma2(hA, vdA2, w23.x); fma2(hA, rrA2, w23.y);
            fma2(hA, ldA2, w45.x); fma2(hA, prA2, w45.y);
            hB = add2(hB, w6x.x);
            fma2(hB, tdB2, w01.x); fma2(hB, pdB2, w01.y);
            fma2(hB, vdB2, w23.x); fma2(hB, rrB2, w23.y);
            fma2(hB, ldB2, w45.x); fma2(hB, prB2, w45.y);

            float2 ha = upk(hA), hb = upk(hB);
            float gA0 = gelu_f(ha.x), gA1 = gelu_f(ha.y);
            float gB0 = gelu_f(hb.x), gB1 = gelu_f(hb.y);
            ull gA02 = pk2(gA0, gA0), gA12 = pk2(gA1, gA1);
            ull gB02 = pk2(gB0, gB0), gB12 = pk2(gB1, gB1);

            const ulonglong2* w2a = (const ulonglong2*)(W2S + (2 * k2) * NN);
            const ulonglong2* w2b = (const ulonglong2*)(W2S + (2 * k2 + 1) * NN);
#pragma unroll
            for (int m = 0; m < 8; m++) {
                ulonglong2 wa = w2a[m];
                fma2(accA[2 * m],     gA02, wa.x);
                fma2(accA[2 * m + 1], gA02, wa.y);
                fma2(accB[2 * m],     gB02, wa.x);
                fma2(accB[2 * m + 1], gB02, wa.y);
                ulonglong2 wb = w2b[m];
                fma2(accA[2 * m],     gA12, wb.x);
                fma2(accA[2 * m + 1], gA12, wb.y);
                fma2(accB[2 * m],     gB12, wb.x);
                fma2(accB[2 * m + 1], gB12, wb.y);
            }
        }

        float eA = b3S, eB = b3S;
#pragma unroll
        for (int m = 0; m < 16; m++) {
            float2 vA = upk(accA[m]);
            float2 vB = upk(accB[m]);
            eA = fmaf(gelu_f(vA.x), W3S[2 * m],     eA);
            eA = fmaf(gelu_f(vA.y), W3S[2 * m + 1], eA);
            eB = fmaf(gelu_f(vB.x), W3S[2 * m],     eB);
            eB = fmaf(gelu_f(vB.y), W3S[2 * m + 1], eB);
        }
        float feA = sigm(eA) * gateA;
        float feB = sigm(eB) * gateB;

        adjS[iA * 33 + jA] = feA;
        adjS[jA * 33 + iA] = feA;
        adjS[iB * 33 + jB] = feB;
        adjS[jB * 33 + iB] = feB;
    }
    if (t < 32) adjS[t * 33 + t] = 0.0f;
    __syncthreads();

    float* outB = out + (size_t)b * (NN * NN);
#pragma unroll
    for (int u = 0; u < 4; u++) {
        int idx = t + u * 256;
        outB[idx] = adjS[(idx >> 5) * 33 + (idx & 31)];
    }
}

// ---------------- launch ----------------
extern "C" void kernel_launch(void* const* d_in, const int* in_sizes, int n_in,
                              void* d_out, int out_size) {
    const float* cel   = (const float*)d_in[0];
    const float* theta = (const float*)d_in[1];
    const float* phi   = (const float*)d_in[2];
    const float* vel   = (const float*)d_in[3];
    const float* rad   = (const float*)d_in[4];
    const float* lon   = (const float*)d_in[5];
    const float* W1    = (const float*)d_in[6];
    const float* b1    = (const float*)d_in[7];
    const float* W2    = (const float*)d_in[8];
    const float* b2    = (const float*)d_in[9];
    const float* W3    = (const float*)d_in[10];
    const float* b3    = (const float*)d_in[11];
    const float* pw    = (const float*)d_in[12];
    float* out = (float*)d_out;

    int B = in_sizes[0] / (SS * NN * DD);
    if (B > BMAX) B = BMAX;

    float* pre;
    cudaGetSymbolAddress((void**)&pre, g_pre);

    pre_kernel<<<B, 256>>>(cel, W1, pre);
    pair_kernel<<<B, 256>>>(pre, theta, phi, vel, rad, lon,
                            W1, b1, W2, b2, W3, b3, pw, out);
}

// round 4
// speedup vs baseline: 2.1563x; 1.0205x over previous
#include <cuda_runtime.h>
#include <math.h>

// Problem constants
#define BMAX 2048
#define SS   8
#define NN   32
#define DD   64
#define NP   496          // 32*31/2

typedef unsigned long long ull;

// Scratch: interleaved layout. As ull (f32 pairs over k,k+1):
// ull index = part*1024 + k2*32 + n   (part: 0 = fi-half, 1 = fj-half)
__device__ float g_pre[(size_t)BMAX * 128 * NN];

// ---------------- packed f32x2 helpers (sm_103a) ----------------
__device__ __forceinline__ ull pk2(float a, float b) {
    ull r; asm("mov.b64 %0, {%1,%2};" : "=l"(r) : "f"(a), "f"(b)); return r;
}
__device__ __forceinline__ void fma2(ull &d, ull a, ull b) {
    asm("fma.rn.f32x2 %0, %1, %2, %0;" : "+l"(d) : "l"(a), "l"(b));
}
__device__ __forceinline__ ull fma2n(ull a, ull b, ull c) {
    ull r; asm("fma.rn.f32x2 %0, %1, %2, %3;" : "=l"(r) : "l"(a), "l"(b), "l"(c)); return r;
}
__device__ __forceinline__ ull add2(ull a, ull b) {
    ull r; asm("add.rn.f32x2 %0, %1, %2;" : "=l"(r) : "l"(a), "l"(b)); return r;
}
__device__ __forceinline__ ull mul2(ull a, ull b) {
    ull r; asm("mul.rn.f32x2 %0, %1, %2;" : "=l"(r) : "l"(a), "l"(b)); return r;
}
__device__ __forceinline__ float2 upk(ull a) {
    float2 f; asm("mov.b64 {%0,%1}, %2;" : "=f"(f.x), "=f"(f.y) : "l"(a)); return f;
}

__device__ __forceinline__ float wrapang(float d) {
    return fmaf(-6.283185307179586f, rintf(d * 0.15915494309189535f), d);
}

// Packed tanh-form gelu on two values:
// gelu(x) = x * (1 - 1/(1 + 2^(x*(A + B*x^2)))),
// A = 0.7978845608*2*log2(e) = 2.3022077, B = A*0.044715 = 0.10294322
__device__ __forceinline__ ull gelu2t(ull h2) {
    const ull A2   = pk2(2.3022077f, 2.3022077f);
    const ull B2   = pk2(0.10294322f, 0.10294322f);
    const ull ONE2 = pk2(1.0f, 1.0f);
    const ull M12  = pk2(-1.0f, -1.0f);
    ull x2 = mul2(h2, h2);
    ull q2 = fma2n(x2, B2, A2);
    ull p2 = mul2(h2, q2);
    float2 p = upk(p2);
    float e0, e1;
    asm("ex2.approx.f32 %0, %1;" : "=f"(e0) : "f"(p.x));
    asm("ex2.approx.f32 %0, %1;" : "=f"(e1) : "f"(p.y));
    ull d2 = add2(pk2(e0, e1), ONE2);
    float2 dv = upk(d2);
    float r0, r1;
    asm("rcp.approx.f32 %0, %1;" : "=f"(r0) : "f"(dv.x));
    asm("rcp.approx.f32 %0, %1;" : "=f"(r1) : "f"(dv.y));
    ull t2 = fma2n(pk2(r0, r1), M12, ONE2);  // 1 - r
    return mul2(h2, t2);
}

__device__ __forceinline__ float sigm(float x) {
    return 1.0f / (1.0f + __expf(-x));
}

// ---------------- Kernel 1: pre (interleaved layout), f32x2, 4 acc chains ----------------
__global__ __launch_bounds__(256)
void pre_kernel(const float* __restrict__ cel, const float* __restrict__ W1,
                float* __restrict__ pre) {
    const int b = blockIdx.x;
    const int t = threadIdx.x;
    const int k = t & 127;       // output column 0..127
    const int half = t >> 7;     // n-range selector

    __shared__ __align__(16) float fS[NN * DD];      // 8 KB
    __shared__ float oS[4096 + 64];                  // padded staging

    const float* feats = cel + (((size_t)b * SS + (SS - 1)) * NN) * DD;
    ((float4*)fS)[t]       = ((const float4*)feats)[t];
    ((float4*)fS)[t + 256] = ((const float4*)feats)[t + 256];

    // packed weight column {W[2d][k], W[2d+1][k]}
    const float* wcol = (k < 64) ? (W1 + k) : (W1 + 64 * 64 + (k - 64));
    ull wk2[32];
#pragma unroll
    for (int d2 = 0; d2 < 32; d2++)
        wk2[d2] = pk2(wcol[(size_t)(2 * d2) * 64], wcol[(size_t)(2 * d2 + 1) * 64]);

    __syncthreads();

    const int kk = k & 63, part = k >> 6, kb = k & 1;
    const int obase = part * 2048 + (kk >> 1) * 64 + kb;

    for (int n = half * 16; n < half * 16 + 16; n++) {
        const ull* fr = (const ull*)(fS + n * DD);
        ull a0 = 0ull, a1 = 0ull, a2 = 0ull, a3 = 0ull;
#pragma unroll
        for (int d2 = 0; d2 < 32; d2 += 4) {
            fma2(a0, fr[d2],     wk2[d2]);
            fma2(a1, fr[d2 + 1], wk2[d2 + 1]);
            fma2(a2, fr[d2 + 2], wk2[d2 + 2]);
            fma2(a3, fr[d2 + 3], wk2[d2 + 3]);
        }
        a0 = add2(a0, a1); a2 = add2(a2, a3); a0 = add2(a0, a2);
        float2 v = upk(a0);
        float a = v.x + v.y;
        int idx = obase + 2 * n;
        oS[idx + (idx >> 6)] = a;    // pad every 64 to break bank conflicts
    }
    __syncthreads();

    float* ob = pre + (size_t)b * 4096;
#pragma unroll
    for (int u = 0; u < 16; u++) {
        int i2 = t + u * 256;
        ob[i2] = oS[i2 + (i2 >> 6)];
    }
}

// ---------------- Kernel 2: 1 pair per thread, 512 threads, packed gelu ----------------
__global__ __launch_bounds__(512, 1)
void pair_kernel(const float* __restrict__ pre,
                 const float* __restrict__ theta, const float* __restrict__ phi,
                 const float* __restrict__ vel,   const float* __restrict__ rad,
                 const float* __restrict__ lon,
                 const float* __restrict__ W1, const float* __restrict__ b1,
                 const float* __restrict__ W2, const float* __restrict__ b2,
                 const float* __restrict__ W3, const float* __restrict__ b3,
                 const float* __restrict__ pw,
                 float* __restrict__ out) {
    const int b = blockIdx.x;
    const int t = threadIdx.x;

    __shared__ __align__(16) ull  preS2[2048];       // 16 KB interleaved pre
    __shared__ __align__(16) float W2S[64 * NN];     // 8 KB
    __shared__ __align__(16) ull  W1cS[32 * 8];      // 2 KB: per k2: 6 coeff pairs, b1 pair, pad
    __shared__ __align__(16) ull  W3S2[16];          // packed W3
    __shared__ float b2S[32], pwS[8];
    __shared__ float thS[32], phS[32], veS[32], raS[32], loS[32];
    __shared__ float cthS[32], sthS[32], cphS[32], sphS[32];
    __shared__ float adjS[32 * 33];
    __shared__ float b3S;

    // ---- stage shared ----
    const float* preB = pre + (size_t)b * 4096;
    ((float4*)preS2)[t]       = ((const float4*)preB)[t];
    ((float4*)preS2)[t + 512] = ((const float4*)preB)[t + 512];
    ((float4*)W2S)[t] = ((const float4*)W2)[t];          // 2048 floats
    if (t < 256) {
        int k2 = t >> 3, s = t & 7, k = 2 * k2;
        float lo = 0.0f, hi = 0.0f;
        if (s < 6)       { lo = W1[(size_t)(128 + s) * 64 + k]; hi = W1[(size_t)(128 + s) * 64 + k + 1]; }
        else if (s == 6) { lo = b1[k]; hi = b1[k + 1]; }
        W1cS[t] = pk2(lo, hi);
    }
    if (t < 32) {
        b2S[t] = b2[t];
        float tht = theta[b * NN + t], pht = phi[b * NN + t];
        thS[t] = tht; phS[t] = pht;
        veS[t] = vel[b * NN + t];
        raS[t] = rad[b * NN + t];
        loS[t] = lon[b * NN + t];
        float s_, c_;
        sincosf(tht, &s_, &c_); sthS[t] = s_; cthS[t] = c_;
        sincosf(pht, &s_, &c_); sphS[t] = s_; cphS[t] = c_;
    }
    if (t < 16) W3S2[t] = pk2(W3[2 * t], W3[2 * t + 1]);
    if (t < 6)  pwS[t] = pw[t];
    if (t == 0) b3S = b3[0];
    __syncthreads();

    if (t < NP) {
        // pair index -> (i, j), i<j
        float pf = (float)t;
        int i = (int)((63.0f - sqrtf(3969.0f - 8.0f * pf)) * 0.5f);
        int base = (i * (63 - i)) >> 1;
        int j = i + 1 + (t - base);

        float td  = wrapang(thS[i] - thS[j]);
        float pd  = wrapang(phS[i] - phS[j]);
        float vd  = veS[i] - veS[j];
        float rr  = __fdividef(raS[i], raS[j] + 1e-8f);
        float ldv = wrapang(loS[i] - loS[j]);
        float pr  = (cthS[i] * cthS[j] + sthS[i] * sthS[j]) *
                    (cphS[i] * cphS[j] + sphS[i] * sphS[j]);

        float gate = sigm(pwS[0] * fabsf(td) + pwS[1] * fabsf(pd) + pwS[2] * fabsf(vd)
                        + pwS[3] * fabsf(rr - 1.0f) + pwS[4] * fabsf(ldv) + pwS[5] * fabsf(pr));

        ull td2 = pk2(td, td), pd2 = pk2(pd, pd), vd2 = pk2(vd, vd);
        ull rr2 = pk2(rr, rr), ld2 = pk2(ldv, ldv), pr2 = pk2(pr, pr);

        ull acc[16];
#pragma unroll
        for (int m = 0; m < 16; m++) acc[m] = pk2(b2S[2 * m], b2S[2 * m + 1]);

        const ull* pFi = preS2 + i;            // + k2*32
        const ull* pFj = preS2 + 1024 + j;     // + k2*32

#pragma unroll 2
        for (int k2 = 0; k2 < 32; k2++) {
            ull h2 = add2(pFi[k2 * 32], pFj[k2 * 32]);
            const ulonglong2* w = (const ulonglong2*)(W1cS + k2 * 8);
            ulonglong2 w01 = w[0], w23 = w[1], w45 = w[2], w6x = w[3];
            h2 = add2(h2, w6x.x);                        // + b1 pair
            fma2(h2, td2, w01.x); fma2(h2, pd2, w01.y);
            fma2(h2, vd2, w23.x); fma2(h2, rr2, w23.y);
            fma2(h2, ld2, w45.x); fma2(h2, pr2, w45.y);

            ull g2 = gelu2t(h2);
            float2 g = upk(g2);
            ull g00 = pk2(g.x, g.x);
            ull g11 = pk2(g.y, g.y);

            const ulonglong2* w2a = (const ulonglong2*)(W2S + (2 * k2) * NN);
            const ulonglong2* w2b = (const ulonglong2*)(W2S + (2 * k2 + 1) * NN);
#pragma unroll
            for (int m = 0; m < 8; m++) {
                ulonglong2 wa = w2a[m];
                fma2(acc[2 * m],     g00, wa.x);
                fma2(acc[2 * m + 1], g00, wa.y);
                ulonglong2 wb = w2b[m];
                fma2(acc[2 * m],     g11, wb.x);
                fma2(acc[2 * m + 1], g11, wb.y);
            }
        }

        // layer-2 gelu (packed) + W3 dot (packed accumulate)
        ull e2 = 0ull;
#pragma unroll
        for (int m = 0; m < 16; m++) {
            ull g2 = gelu2t(acc[m]);
            fma2(e2, g2, W3S2[m]);
        }
        float2 ev = upk(e2);
        float e = b3S + ev.x + ev.y;
        float fe = sigm(e) * gate;

        adjS[i * 33 + j] = fe;
        adjS[j * 33 + i] = fe;
    }
    if (t < 32) adjS[t * 33 + t] = 0.0f;
    __syncthreads();

    float* outB = out + (size_t)b * (NN * NN);
    {
        int idx = t;
        outB[idx] = adjS[(idx >> 5) * 33 + (idx & 31)];
        idx = t + 512;
        outB[idx] = adjS[(idx >> 5) * 33 + (idx & 31)];
    }
}

// ---------------- launch ----------------
extern "C" void kernel_launch(void* const* d_in, const int* in_sizes, int n_in,
                              void* d_out, int out_size) {
    const float* cel   = (const float*)d_in[0];
    const float* theta = (const float*)d_in[1];
    const float* phi   = (const float*)d_in[2];
    const float* vel   = (const float*)d_in[3];
    const float* rad   = (const float*)d_in[4];
    const float* lon   = (const float*)d_in[5];
    const float* W1    = (const float*)d_in[6];
    const float* b1    = (const float*)d_in[7];
    const float* W2    = (const float*)d_in[8];
    const float* b2    = (const float*)d_in[9];
    const float* W3    = (const float*)d_in[10];
    const float* b3    = (const float*)d_in[11];
    const float* pw    = (const float*)d_in[12];
    float* out = (float*)d_out;

    int B = in_sizes[0] / (SS * NN * DD);
    if (B > BMAX) B = BMAX;

    float* pre;
    cudaGetSymbolAddress((void**)&pre, g_pre);

    pre_kernel<<<B, 256>>>(cel, W1, pre);
    pair_kernel<<<B, 512>>>(pre, theta, phi, vel, rad, lon,
                            W1, b1, W2, b2, W3, b3, pw, out);
}

// round 9
// speedup vs baseline: 2.2395x; 1.0386x over previous
#include <cuda_runtime.h>
#include <math.h>

// Problem constants
#define BMAX 2048
#define SS   8
#define NN   32
#define DD   64
#define NP   496          // 32*31/2

typedef unsigned long long ull;

// Scratch: interleaved layout. As ull (f32 pairs over k,k+1):
// ull index = part*1024 + k2*32 + n   (part: 0 = fi-half, 1 = fj-half)
__device__ float g_pre[(size_t)BMAX * 128 * NN];

// ---------------- packed f32x2 helpers (sm_103a) ----------------
__device__ __forceinline__ ull pk2(float a, float b) {
    ull r; asm("mov.b64 %0, {%1,%2};" : "=l"(r) : "f"(a), "f"(b)); return r;
}
__device__ __forceinline__ void fma2(ull &d, ull a, ull b) {
    asm("fma.rn.f32x2 %0, %1, %2, %0;" : "+l"(d) : "l"(a), "l"(b));
}
__device__ __forceinline__ ull fma2n(ull a, ull b, ull c) {
    ull r; asm("fma.rn.f32x2 %0, %1, %2, %3;" : "=l"(r) : "l"(a), "l"(b), "l"(c)); return r;
}
__device__ __forceinline__ ull add2(ull a, ull b) {
    ull r; asm("add.rn.f32x2 %0, %1, %2;" : "=l"(r) : "l"(a), "l"(b)); return r;
}
__device__ __forceinline__ ull mul2(ull a, ull b) {
    ull r; asm("mul.rn.f32x2 %0, %1, %2;" : "=l"(r) : "l"(a), "l"(b)); return r;
}
__device__ __forceinline__ float2 upk(ull a) {
    float2 f; asm("mov.b64 {%0,%1}, %2;" : "=f"(f.x), "=f"(f.y) : "l"(a)); return f;
}

__device__ __forceinline__ float wrapang(float d) {
    return fmaf(-6.283185307179586f, rintf(d * 0.15915494309189535f), d);
}

// Packed tanh-form gelu on two values:
// gelu(x) = x * (1 - 1/(1 + 2^(x*(A + B*x^2))))
__device__ __forceinline__ ull gelu2t(ull h2) {
    const ull A2   = pk2(2.3022077f, 2.3022077f);
    const ull B2   = pk2(0.10294322f, 0.10294322f);
    const ull ONE2 = pk2(1.0f, 1.0f);
    const ull M12  = pk2(-1.0f, -1.0f);
    ull x2 = mul2(h2, h2);
    ull q2 = fma2n(x2, B2, A2);
    ull p2 = mul2(h2, q2);
    float2 p = upk(p2);
    float e0, e1;
    asm("ex2.approx.f32 %0, %1;" : "=f"(e0) : "f"(p.x));
    asm("ex2.approx.f32 %0, %1;" : "=f"(e1) : "f"(p.y));
    ull d2 = add2(pk2(e0, e1), ONE2);
    float2 dv = upk(d2);
    float r0, r1;
    asm("rcp.approx.f32 %0, %1;" : "=f"(r0) : "f"(dv.x));
    asm("rcp.approx.f32 %0, %1;" : "=f"(r1) : "f"(dv.y));
    ull t2 = fma2n(pk2(r0, r1), M12, ONE2);  // 1 - r
    return mul2(h2, t2);
}

__device__ __forceinline__ float sigm(float x) {
    return 1.0f / (1.0f + __expf(-x));
}

// ---------------- Kernel 1: pre (interleaved layout), f32x2, 4 acc chains ----------------
__global__ __launch_bounds__(256)
void pre_kernel(const float* __restrict__ cel, const float* __restrict__ W1,
                float* __restrict__ pre) {
    const int b = blockIdx.x;
    const int t = threadIdx.x;
    const int k = t & 127;       // output column 0..127
    const int half = t >> 7;     // n-range selector

    __shared__ __align__(16) float fS[NN * DD];      // 8 KB
    __shared__ float oS[4096 + 64];                  // padded staging

    const float* feats = cel + (((size_t)b * SS + (SS - 1)) * NN) * DD;
    ((float4*)fS)[t]       = ((const float4*)feats)[t];
    ((float4*)fS)[t + 256] = ((const float4*)feats)[t + 256];

    // packed weight column {W[2d][k], W[2d+1][k]}
    const float* wcol = (k < 64) ? (W1 + k) : (W1 + 64 * 64 + (k - 64));
    ull wk2[32];
#pragma unroll
    for (int d2 = 0; d2 < 32; d2++)
        wk2[d2] = pk2(wcol[(size_t)(2 * d2) * 64], wcol[(size_t)(2 * d2 + 1) * 64]);

    __syncthreads();

    const int kk = k & 63, part = k >> 6, kb = k & 1;
    const int obase = part * 2048 + (kk >> 1) * 64 + kb;

    for (int n = half * 16; n < half * 16 + 16; n++) {
        const ull* fr = (const ull*)(fS + n * DD);
        ull a0 = 0ull, a1 = 0ull, a2 = 0ull, a3 = 0ull;
#pragma unroll
        for (int d2 = 0; d2 < 32; d2 += 4) {
            fma2(a0, fr[d2],     wk2[d2]);
            fma2(a1, fr[d2 + 1], wk2[d2 + 1]);
            fma2(a2, fr[d2 + 2], wk2[d2 + 2]);
            fma2(a3, fr[d2 + 3], wk2[d2 + 3]);
        }
        a0 = add2(a0, a1); a2 = add2(a2, a3); a0 = add2(a0, a2);
        float2 v = upk(a0);
        float a = v.x + v.y;
        int idx = obase + 2 * n;
        oS[idx + (idx >> 6)] = a;    // pad every 64 to break bank conflicts
    }
    __syncthreads();

    float* ob = pre + (size_t)b * 4096;
#pragma unroll
    for (int u = 0; u < 16; u++) {
        int i2 = t + u * 256;
        ob[i2] = oS[i2 + (i2 >> 6)];
    }
}

// ---------------- Kernel 2: 2 pairs per thread, 256 threads, packed gelu ----------------
__global__ __launch_bounds__(256, 1)
void pair_kernel(const float* __restrict__ pre,
                 const float* __restrict__ theta, const float* __restrict__ phi,
                 const float* __restrict__ vel,   const float* __restrict__ rad,
                 const float* __restrict__ lon,
                 const float* __restrict__ W1, const float* __restrict__ b1,
                 const float* __restrict__ W2, const float* __restrict__ b2,
                 const float* __restrict__ W3, const float* __restrict__ b3,
                 const float* __restrict__ pw,
                 float* __restrict__ out) {
    const int b = blockIdx.x;
    const int t = threadIdx.x;

    __shared__ __align__(16) ull  preS2[2048];       // 16 KB interleaved pre
    __shared__ __align__(16) float W2S[64 * NN];     // 8 KB
    __shared__ __align__(16) ull  W1cS[32 * 8];      // 2 KB: per k2: 6 coeff pairs, b1 pair, pad
    __shared__ __align__(16) ull  W3S2[16];          // packed W3
    __shared__ float b2S[32], pwS[8];
    __shared__ float thS[32], phS[32], veS[32], raS[32], loS[32];
    __shared__ float cthS[32], sthS[32], cphS[32], sphS[32];
    __shared__ float adjS[32 * 33];
    __shared__ float b3S;

    // ---- stage shared ----
    const float* preB = pre + (size_t)b * 4096;
#pragma unroll
    for (int u = 0; u < 4; u++)
        ((float4*)preS2)[t + u * 256] = ((const float4*)preB)[t + u * 256];
    ((float4*)W2S)[t]       = ((const float4*)W2)[t];
    ((float4*)W2S)[t + 256] = ((const float4*)W2)[t + 256];
    {
        int k2 = t >> 3, s = t & 7, k = 2 * k2;
        float lo = 0.0f, hi = 0.0f;
        if (s < 6)       { lo = W1[(size_t)(128 + s) * 64 + k]; hi = W1[(size_t)(128 + s) * 64 + k + 1]; }
        else if (s == 6) { lo = b1[k]; hi = b1[k + 1]; }
        W1cS[t] = pk2(lo, hi);
    }
    if (t < 32) {
        b2S[t] = b2[t];
        float tht = theta[b * NN + t], pht = phi[b * NN + t];
        thS[t] = tht; phS[t] = pht;
        veS[t] = vel[b * NN + t];
        raS[t] = rad[b * NN + t];
        loS[t] = lon[b * NN + t];
        float s_, c_;
        sincosf(tht, &s_, &c_); sthS[t] = s_; cthS[t] = c_;
        sincosf(pht, &s_, &c_); sphS[t] = s_; cphS[t] = c_;
    }
    if (t < 16) W3S2[t] = pk2(W3[2 * t], W3[2 * t + 1]);
    if (t < 6)  pwS[t] = pw[t];
    if (t == 0) b3S = b3[0];
    __syncthreads();

    if (t < 248) {
        // two pairs: pA = t, pB = t + 248
        int iA, jA, iB, jB;
        {
            float pf = (float)t;
            iA = (int)((63.0f - sqrtf(3969.0f - 8.0f * pf)) * 0.5f);
            jA = iA + 1 + (t - ((iA * (63 - iA)) >> 1));
            int tb = t + 248;
            pf = (float)tb;
            iB = (int)((63.0f - sqrtf(3969.0f - 8.0f * pf)) * 0.5f);
            jB = iB + 1 + (tb - ((iB * (63 - iB)) >> 1));
        }

        float tdA = wrapang(thS[iA] - thS[jA]);
        float pdA = wrapang(phS[iA] - phS[jA]);
        float vdA = veS[iA] - veS[jA];
        float rrA = __fdividef(raS[iA], raS[jA] + 1e-8f);
        float ldA = wrapang(loS[iA] - loS[jA]);
        float prA = (cthS[iA] * cthS[jA] + sthS[iA] * sthS[jA]) *
                    (cphS[iA] * cphS[jA] + sphS[iA] * sphS[jA]);
        float tdB = wrapang(thS[iB] - thS[jB]);
        float pdB = wrapang(phS[iB] - phS[jB]);
        float vdB = veS[iB] - veS[jB];
        float rrB = __fdividef(raS[iB], raS[jB] + 1e-8f);
        float ldB = wrapang(loS[iB] - loS[jB]);
        float prB = (cthS[iB] * cthS[jB] + sthS[iB] * sthS[jB]) *
                    (cphS[iB] * cphS[jB] + sphS[iB] * sphS[jB]);

        float gateA = sigm(pwS[0] * fabsf(tdA) + pwS[1] * fabsf(pdA) + pwS[2] * fabsf(vdA)
                         + pwS[3] * fabsf(rrA - 1.0f) + pwS[4] * fabsf(ldA) + pwS[5] * fabsf(prA));
        float gateB = sigm(pwS[0] * fabsf(tdB) + pwS[1] * fabsf(pdB) + pwS[2] * fabsf(vdB)
                         + pwS[3] * fabsf(rrB - 1.0f) + pwS[4] * fabsf(ldB) + pwS[5] * fabsf(prB));

        ull tdA2 = pk2(tdA, tdA), pdA2 = pk2(pdA, pdA), vdA2 = pk2(vdA, vdA);
        ull rrA2 = pk2(rrA, rrA), ldA2 = pk2(ldA, ldA), prA2 = pk2(prA, prA);
        ull tdB2 = pk2(tdB, tdB), pdB2 = pk2(pdB, pdB), vdB2 = pk2(vdB, vdB);
        ull rrB2 = pk2(rrB, rrB), ldB2 = pk2(ldB, ldB), prB2 = pk2(prB, prB);

        ull accA[16], accB[16];
#pragma unroll
        for (int m = 0; m < 16; m++) {
            ull b0 = pk2(b2S[2 * m], b2S[2 * m + 1]);
            accA[m] = b0; accB[m] = b0;
        }

        const ull* pFiA = preS2 + iA;
        const ull* pFjA = preS2 + 1024 + jA;
        const ull* pFiB = preS2 + iB;
        const ull* pFjB = preS2 + 1024 + jB;

#pragma unroll 1
        for (int k2 = 0; k2 < 32; k2++) {
            ull hA = add2(pFiA[k2 * 32], pFjA[k2 * 32]);
            ull hB = add2(pFiB[k2 * 32], pFjB[k2 * 32]);
            const ulonglong2* w = (const ulonglong2*)(W1cS + k2 * 8);
            ulonglong2 w01 = w[0], w23 = w[1], w45 = w[2], w6x = w[3];
            hA = add2(hA, w6x.x);
            hB = add2(hB, w6x.x);
            fma2(hA, tdA2, w01.x); fma2(hB, tdB2, w01.x);
            fma2(hA, pdA2, w01.y); fma2(hB, pdB2, w01.y);
            fma2(hA, vdA2, w23.x); fma2(hB, vdB2, w23.x);
            fma2(hA, rrA2, w23.y); fma2(hB, rrB2, w23.y);
            fma2(hA, ldA2, w45.x); fma2(hB, ldB2, w45.x);
            fma2(hA, prA2, w45.y); fma2(hB, prB2, w45.y);

            ull gA2 = gelu2t(hA);
            ull gB2 = gelu2t(hB);
            float2 ga = upk(gA2), gb = upk(gB2);
            ull gA00 = pk2(ga.x, ga.x), gA11 = pk2(ga.y, ga.y);
            ull gB00 = pk2(gb.x, gb.x), gB11 = pk2(gb.y, gb.y);

            const ulonglong2* w2a = (const ulonglong2*)(W2S + (2 * k2) * NN);
            const ulonglong2* w2b = (const ulonglong2*)(W2S + (2 * k2 + 1) * NN);
#pragma unroll
            for (int m = 0; m < 8; m++) {
                ulonglong2 wa = w2a[m];
                fma2(accA[2 * m],     gA00, wa.x);
                fma2(accA[2 * m + 1], gA00, wa.y);
                fma2(accB[2 * m],     gB00, wa.x);
                fma2(accB[2 * m + 1], gB00, wa.y);
                ulonglong2 wb = w2b[m];
                fma2(accA[2 * m],     gA11, wb.x);
                fma2(accA[2 * m + 1], gA11, wb.y);
                fma2(accB[2 * m],     gB11, wb.x);
                fma2(accB[2 * m + 1], gB11, wb.y);
            }
        }

        // epilogue: packed layer-2 gelu + W3 dot, A then B to cap liveness
        ull e2 = 0ull;
#pragma unroll
        for (int m = 0; m < 16; m++) fma2(e2, gelu2t(accA[m]), W3S2[m]);
        float2 ev = upk(e2);
        float feA = sigm(b3S + ev.x + ev.y) * gateA;

        e2 = 0ull;
#pragma unroll
        for (int m = 0; m < 16; m++) fma2(e2, gelu2t(accB[m]), W3S2[m]);
        ev = upk(e2);
        float feB = sigm(b3S + ev.x + ev.y) * gateB;

        adjS[iA * 33 + jA] = feA;
        adjS[jA * 33 + iA] = feA;
        adjS[iB * 33 + jB] = feB;
        adjS[jB * 33 + iB] = feB;
    }
    if (t < 32) adjS[t * 33 + t] = 0.0f;
    __syncthreads();

    float* outB = out + (size_t)b * (NN * NN);
#pragma unroll
    for (int u = 0; u < 4; u++) {
        int idx = t + u * 256;
        outB[idx] = adjS[(idx >> 5) * 33 + (idx & 31)];
    }
}

// ---------------- launch ----------------
extern "C" void kernel_launch(void* const* d_in, const int* in_sizes, int n_in,
                              void* d_out, int out_size) {
    const float* cel   = (const float*)d_in[0];
    const float* theta = (const float*)d_in[1];
    const float* phi   = (const float*)d_in[2];
    const float* vel   = (const float*)d_in[3];
    const float* rad   = (const float*)d_in[4];
    const float* lon   = (const float*)d_in[5];
    const float* W1    = (const float*)d_in[6];
    const float* b1    = (const float*)d_in[7];
    const float* W2    = (const float*)d_in[8];
    const float* b2    = (const float*)d_in[9];
    const float* W3    = (const float*)d_in[10];
    const float* b3    = (const float*)d_in[11];
    const float* pw    = (const float*)d_in[12];
    float* out = (float*)d_out;

    int B = in_sizes[0] / (SS * NN * DD);
    if (B > BMAX) B = BMAX;

    float* pre;
    cudaGetSymbolAddress((void**)&pre, g_pre);

    pre_kernel<<<B, 256>>>(cel, W1, pre);
    pair_kernel<<<B, 256>>>(pre, theta, phi, vel, rad, lon,
                            W1, b1, W2, b2, W3, b3, pw, out);
}

// round 14
// speedup vs baseline: 2.5224x; 1.1263x over previous
#include <cuda_runtime.h>
#include <math.h>

// Problem constants
#define BMAX 2048
#define SS   8
#define NN   32
#define DD   64
#define NP   496          // 32*31/2

typedef unsigned long long ull;

// Scratch: interleaved layout. As ull (f32 pairs over k,k+1):
// ull index = part*1024 + k2*32 + n   (part: 0 = fi-half, 1 = fj-half)
__device__ float g_pre[(size_t)BMAX * 128 * NN];

// ---------------- packed f32x2 helpers (sm_103a) ----------------
__device__ __forceinline__ ull pk2(float a, float b) {
    ull r; asm("mov.b64 %0, {%1,%2};" : "=l"(r) : "f"(a), "f"(b)); return r;
}
__device__ __forceinline__ void fma2(ull &d, ull a, ull b) {
    asm("fma.rn.f32x2 %0, %1, %2, %0;" : "+l"(d) : "l"(a), "l"(b));
}
__device__ __forceinline__ ull fma2n(ull a, ull b, ull c) {
    ull r; asm("fma.rn.f32x2 %0, %1, %2, %3;" : "=l"(r) : "l"(a), "l"(b), "l"(c)); return r;
}
__device__ __forceinline__ ull add2(ull a, ull b) {
    ull r; asm("add.rn.f32x2 %0, %1, %2;" : "=l"(r) : "l"(a), "l"(b)); return r;
}
__device__ __forceinline__ ull mul2(ull a, ull b) {
    ull r; asm("mul.rn.f32x2 %0, %1, %2;" : "=l"(r) : "l"(a), "l"(b)); return r;
}
__device__ __forceinline__ float2 upk(ull a) {
    float2 f; asm("mov.b64 {%0,%1}, %2;" : "=f"(f.x), "=f"(f.y) : "l"(a)); return f;
}

__device__ __forceinline__ float wrapang(float d) {
    return fmaf(-6.283185307179586f, rintf(d * 0.15915494309189535f), d);
}

// Packed tanh-form gelu on two values:
// gelu(x) = x * (1 - 1/(1 + 2^(x*(A + B*x^2))))
__device__ __forceinline__ ull gelu2t(ull h2) {
    const ull A2   = pk2(2.3022077f, 2.3022077f);
    const ull B2   = pk2(0.10294322f, 0.10294322f);
    const ull ONE2 = pk2(1.0f, 1.0f);
    const ull M12  = pk2(-1.0f, -1.0f);
    ull x2 = mul2(h2, h2);
    ull q2 = fma2n(x2, B2, A2);
    ull p2 = mul2(h2, q2);
    float2 p = upk(p2);
    float e0, e1;
    asm("ex2.approx.f32 %0, %1;" : "=f"(e0) : "f"(p.x));
    asm("ex2.approx.f32 %0, %1;" : "=f"(e1) : "f"(p.y));
    ull d2 = add2(pk2(e0, e1), ONE2);
    float2 dv = upk(d2);
    float r0, r1;
    asm("rcp.approx.f32 %0, %1;" : "=f"(r0) : "f"(dv.x));
    asm("rcp.approx.f32 %0, %1;" : "=f"(r1) : "f"(dv.y));
    ull t2 = fma2n(pk2(r0, r1), M12, ONE2);  // 1 - r
    return mul2(h2, t2);
}

__device__ __forceinline__ float sigm(float x) {
    return 1.0f / (1.0f + __expf(-x));
}

// ---------------- Kernel 1: pre (interleaved layout), f32x2, 4 acc chains ----------------
__global__ __launch_bounds__(256)
void pre_kernel(const float* __restrict__ cel, const float* __restrict__ W1,
                float* __restrict__ pre) {
    const int b = blockIdx.x;
    const int t = threadIdx.x;
    const int k = t & 127;       // output column 0..127
    const int half = t >> 7;     // n-range selector

    __shared__ __align__(16) float fS[NN * DD];      // 8 KB
    __shared__ float oS[4096 + 64];                  // padded staging

    const float* feats = cel + (((size_t)b * SS + (SS - 1)) * NN) * DD;
    ((float4*)fS)[t]       = ((const float4*)feats)[t];
    ((float4*)fS)[t + 256] = ((const float4*)feats)[t + 256];

    // packed weight column {W[2d][k], W[2d+1][k]}
    const float* wcol = (k < 64) ? (W1 + k) : (W1 + 64 * 64 + (k - 64));
    ull wk2[32];
#pragma unroll
    for (int d2 = 0; d2 < 32; d2++)
        wk2[d2] = pk2(wcol[(size_t)(2 * d2) * 64], wcol[(size_t)(2 * d2 + 1) * 64]);

    __syncthreads();

    const int kk = k & 63, part = k >> 6, kb = k & 1;
    const int obase = part * 2048 + (kk >> 1) * 64 + kb;

    for (int n = half * 16; n < half * 16 + 16; n++) {
        const ull* fr = (const ull*)(fS + n * DD);
        ull a0 = 0ull, a1 = 0ull, a2 = 0ull, a3 = 0ull;
#pragma unroll
        for (int d2 = 0; d2 < 32; d2 += 4) {
            fma2(a0, fr[d2],     wk2[d2]);
            fma2(a1, fr[d2 + 1], wk2[d2 + 1]);
            fma2(a2, fr[d2 + 2], wk2[d2 + 2]);
            fma2(a3, fr[d2 + 3], wk2[d2 + 3]);
        }
        a0 = add2(a0, a1); a2 = add2(a2, a3); a0 = add2(a0, a2);
        float2 v = upk(a0);
        float a = v.x + v.y;
        int idx = obase + 2 * n;
        oS[idx + (idx >> 6)] = a;    // pad every 64 to break bank conflicts
    }
    __syncthreads();

    float* ob = pre + (size_t)b * 4096;
#pragma unroll
    for (int u = 0; u < 16; u++) {
        int i2 = t + u * 256;
        ob[i2] = oS[i2 + (i2 >> 6)];
    }
}

// ---------------- Kernel 2: 2 pairs/thread, 256 threads, 2 CTAs/SM ----------------
__global__ __launch_bounds__(256, 2)
void pair_kernel(const float* __restrict__ pre,
                 const float* __restrict__ theta, const float* __restrict__ phi,
                 const float* __restrict__ vel,   const float* __restrict__ rad,
                 const float* __restrict__ lon,
                 const float* __restrict__ W1, const float* __restrict__ b1,
                 const float* __restrict__ W2, const float* __restrict__ b2,
                 const float* __restrict__ W3, const float* __restrict__ b3,
                 const float* __restrict__ pw,
                 float* __restrict__ out) {
    const int b = blockIdx.x;
    const int t = threadIdx.x;

    __shared__ __align__(16) ull  preS2[2048];       // 16 KB interleaved pre
    __shared__ __align__(16) float W2S[64 * NN];     // 8 KB
    __shared__ __align__(16) ull  W1cS[32 * 8];      // 2 KB: per k2: 6 coeff pairs, b1 pair, pad
    __shared__ __align__(16) ull  W3S2[16];          // packed W3
    __shared__ float b2S[32], pwS[8];
    __shared__ float thS[32], phS[32], veS[32], raS[32], loS[32];
    __shared__ float cthS[32], sthS[32], cphS[32], sphS[32];
    __shared__ float adjS[32 * 33];
    __shared__ float b3S;

    // ---- stage shared ----
    const float* preB = pre + (size_t)b * 4096;
#pragma unroll
    for (int u = 0; u < 4; u++)
        ((float4*)preS2)[t + u * 256] = ((const float4*)preB)[t + u * 256];
    ((float4*)W2S)[t]       = ((const float4*)W2)[t];
    ((float4*)W2S)[t + 256] = ((const float4*)W2)[t + 256];
    {
        int k2 = t >> 3, s = t & 7, k = 2 * k2;
        float lo = 0.0f, hi = 0.0f;
        if (s < 6)       { lo = W1[(size_t)(128 + s) * 64 + k]; hi = W1[(size_t)(128 + s) * 64 + k + 1]; }
        else if (s == 6) { lo = b1[k]; hi = b1[k + 1]; }
        W1cS[t] = pk2(lo, hi);
    }
    if (t < 32) {
        b2S[t] = b2[t];
        float tht = theta[b * NN + t], pht = phi[b * NN + t];
        thS[t] = tht; phS[t] = pht;
        veS[t] = vel[b * NN + t];
        raS[t] = rad[b * NN + t];
        loS[t] = lon[b * NN + t];
        float s_, c_;
        sincosf(tht, &s_, &c_); sthS[t] = s_; cthS[t] = c_;
        sincosf(pht, &s_, &c_); sphS[t] = s_; cphS[t] = c_;
    }
    if (t < 16) W3S2[t] = pk2(W3[2 * t], W3[2 * t + 1]);
    if (t < 6)  pwS[t] = pw[t];
    if (t == 0) b3S = b3[0];
    __syncthreads();

    if (t < 248) {
        // two pairs: pA = t, pB = t + 248
        int iA, jA, iB, jB;
        {
            float pf = (float)t;
            iA = (int)((63.0f - sqrtf(3969.0f - 8.0f * pf)) * 0.5f);
            jA = iA + 1 + (t - ((iA * (63 - iA)) >> 1));
            int tb = t + 248;
            pf = (float)tb;
            iB = (int)((63.0f - sqrtf(3969.0f - 8.0f * pf)) * 0.5f);
            jB = iB + 1 + (tb - ((iB * (63 - iB)) >> 1));
        }

        // packed per-pair features only (scalars not kept live; gates computed at end)
        ull tdA2, pdA2, vdA2, rrA2, ldA2, prA2;
        ull tdB2, pdB2, vdB2, rrB2, ldB2, prB2;
        {
            float td = wrapang(thS[iA] - thS[jA]);
            float pd = wrapang(phS[iA] - phS[jA]);
            float vd = veS[iA] - veS[jA];
            float rr = __fdividef(raS[iA], raS[jA] + 1e-8f);
            float ld = wrapang(loS[iA] - loS[jA]);
            float pr = (cthS[iA] * cthS[jA] + sthS[iA] * sthS[jA]) *
                       (cphS[iA] * cphS[jA] + sphS[iA] * sphS[jA]);
            tdA2 = pk2(td, td); pdA2 = pk2(pd, pd); vdA2 = pk2(vd, vd);
            rrA2 = pk2(rr, rr); ldA2 = pk2(ld, ld); prA2 = pk2(pr, pr);
        }
        {
            float td = wrapang(thS[iB] - thS[jB]);
            float pd = wrapang(phS[iB] - phS[jB]);
            float vd = veS[iB] - veS[jB];
            float rr = __fdividef(raS[iB], raS[jB] + 1e-8f);
            float ld = wrapang(loS[iB] - loS[jB]);
            float pr = (cthS[iB] * cthS[jB] + sthS[iB] * sthS[jB]) *
                       (cphS[iB] * cphS[jB] + sphS[iB] * sphS[jB]);
            tdB2 = pk2(td, td); pdB2 = pk2(pd, pd); vdB2 = pk2(vd, vd);
            rrB2 = pk2(rr, rr); ldB2 = pk2(ld, ld); prB2 = pk2(pr, pr);
        }

        ull accA[16], accB[16];
#pragma unroll
        for (int m = 0; m < 16; m++) {
            ull b0 = pk2(b2S[2 * m], b2S[2 * m + 1]);
            accA[m] = b0; accB[m] = b0;
        }

        const ull* pFiA = preS2 + iA;
        const ull* pFjA = preS2 + 1024 + jA;
        const ull* pFiB = preS2 + iB;
        const ull* pFjB = preS2 + 1024 + jB;

#pragma unroll 1
        for (int k2 = 0; k2 < 32; k2++) {
            ull b1p = W1cS[k2 * 8 + 6];
            ull hA = add2(add2(pFiA[k2 * 32], pFjA[k2 * 32]), b1p);
            ull hB = add2(add2(pFiB[k2 * 32], pFjB[k2 * 32]), b1p);
            const ulonglong2* w = (const ulonglong2*)(W1cS + k2 * 8);
            ulonglong2 w01 = w[0], w23 = w[1], w45 = w[2];
            fma2(hA, tdA2, w01.x); fma2(hB, tdB2, w01.x);
            fma2(hA, pdA2, w01.y); fma2(hB, pdB2, w01.y);
            fma2(hA, vdA2, w23.x); fma2(hB, vdB2, w23.x);
            fma2(hA, rrA2, w23.y); fma2(hB, rrB2, w23.y);
            fma2(hA, ldA2, w45.x); fma2(hB, ldB2, w45.x);
            fma2(hA, prA2, w45.y); fma2(hB, prB2, w45.y);

            ull gA2 = gelu2t(hA);
            ull gB2 = gelu2t(hB);
            float2 ga = upk(gA2), gb = upk(gB2);
            ull gA00 = pk2(ga.x, ga.x), gA11 = pk2(ga.y, ga.y);
            ull gB00 = pk2(gb.x, gb.x), gB11 = pk2(gb.y, gb.y);

            const ulonglong2* w2a = (const ulonglong2*)(W2S + (2 * k2) * NN);
            const ulonglong2* w2b = (const ulonglong2*)(W2S + (2 * k2 + 1) * NN);
#pragma unroll
            for (int m = 0; m < 8; m++) {
                ulonglong2 wa = w2a[m];
                fma2(accA[2 * m],     gA00, wa.x);
                fma2(accA[2 * m + 1], gA00, wa.y);
                fma2(accB[2 * m],     gB00, wa.x);
                fma2(accB[2 * m + 1], gB00, wa.y);
                ulonglong2 wb = w2b[m];
                fma2(accA[2 * m],     gA11, wb.x);
                fma2(accA[2 * m + 1], gA11, wb.y);
                fma2(accB[2 * m],     gB11, wb.x);
                fma2(accB[2 * m + 1], gB11, wb.y);
            }
        }

        // gates recovered from packed feature lanes (kept out of the loop's live set)
        float gateA, gateB;
        {
            float td = upk(tdA2).x, pd = upk(pdA2).x, vd = upk(vdA2).x;
            float rr = upk(rrA2).x, ld = upk(ldA2).x, pr = upk(prA2).x;
            gateA = sigm(pwS[0] * fabsf(td) + pwS[1] * fabsf(pd) + pwS[2] * fabsf(vd)
                       + pwS[3] * fabsf(rr - 1.0f) + pwS[4] * fabsf(ld) + pwS[5] * fabsf(pr));
            td = upk(tdB2).x; pd = upk(pdB2).x; vd = upk(vdB2).x;
            rr = upk(rrB2).x; ld = upk(ldB2).x; pr = upk(prB2).x;
            gateB = sigm(pwS[0] * fabsf(td) + pwS[1] * fabsf(pd) + pwS[2] * fabsf(vd)
                       + pwS[3] * fabsf(rr - 1.0f) + pwS[4] * fabsf(ld) + pwS[5] * fabsf(pr));
        }

        // epilogue: packed layer-2 gelu + W3 dot, A then B to cap liveness
        ull e2 = 0ull;
#pragma unroll
        for (int m = 0; m < 16; m++) fma2(e2, gelu2t(accA[m]), W3S2[m]);
        float2 ev = upk(e2);
        float feA = sigm(b3S + ev.x + ev.y) * gateA;

        e2 = 0ull;
#pragma unroll
        for (int m = 0; m < 16; m++) fma2(e2, gelu2t(accB[m]), W3S2[m]);
        ev = upk(e2);
        float feB = sigm(b3S + ev.x + ev.y) * gateB;

        adjS[iA * 33 + jA] = feA;
        adjS[jA * 33 + iA] = feA;
        adjS[iB * 33 + jB] = feB;
        adjS[jB * 33 + iB] = feB;
    }
    if (t < 32) adjS[t * 33 + t] = 0.0f;
    __syncthreads();

    float* outB = out + (size_t)b * (NN * NN);
#pragma unroll
    for (int u = 0; u < 4; u++) {
        int idx = t + u * 256;
        outB[idx] = adjS[(idx >> 5) * 33 + (idx & 31)];
    }
}

// ---------------- launch ----------------
extern "C" void kernel_launch(void* const* d_in, const int* in_sizes, int n_in,
                              void* d_out, int out_size) {
    const float* cel   = (const float*)d_in[0];
    const float* theta = (const float*)d_in[1];
    const float* phi   = (const float*)d_in[2];
    const float* vel   = (const float*)d_in[3];
    const float* rad   = (const float*)d_in[4];
    const float* lon   = (const float*)d_in[5];
    const float* W1    = (const float*)d_in[6];
    const float* b1    = (const float*)d_in[7];
    const float* W2    = (const float*)d_in[8];
    const float* b2    = (const float*)d_in[9];
    const float* W3    = (const float*)d_in[10];
    const float* b3    = (const float*)d_in[11];
    const float* pw    = (const float*)d_in[12];
    float* out = (float*)d_out;

    int B = in_sizes[0] / (SS * NN * DD);
    if (B > BMAX) B = BMAX;

    float* pre;
    cudaGetSymbolAddress((void**)&pre, g_pre);

    pre_kernel<<<B, 256>>>(cel, W1, pre);
    pair_kernel<<<B, 256>>>(pre, theta, phi, vel, rad, lon,
                            W1, b1, W2, b2, W3, b3, pw, out);
}